// round 14
// baseline (speedup 1.0000x reference)
#include <cuda_runtime.h>
#include <cuda_bf16.h>
#include <cstdint>
#include <math.h>

// ---------------- problem constants ----------------
#define BATCH   128
#define NTOK    394
#define EMBD    256
#define NP      196
#define HEADS   2
#define DH      128
#define K1      768
#define K2      192
#define ROWS_E  (BATCH*NP)         // 25088
#define ROWS_T  (BATCH*NTOK)       // 50432

// ---------------- scratch ----------------
__device__ __nv_bfloat16 g_p1h[(size_t)ROWS_E * K1];
__device__ __nv_bfloat16 g_p1l[(size_t)ROWS_E * K1];
__device__ __nv_bfloat16 g_p2h[(size_t)ROWS_E * K2];
__device__ __nv_bfloat16 g_p2l[(size_t)ROWS_E * K2];
__device__ __nv_bfloat16 g_hh [(size_t)ROWS_T * EMBD];
__device__ __nv_bfloat16 g_hl [(size_t)ROWS_T * EMBD];
__device__ __nv_bfloat16 g_oh [(size_t)ROWS_T * EMBD];
__device__ __nv_bfloat16 g_ol [(size_t)ROWS_T * EMBD];
__device__ __nv_bfloat16 g_qkvh[(size_t)ROWS_T * 768];
__device__ __nv_bfloat16 g_qkvl[(size_t)ROWS_T * 768];
__device__ __nv_bfloat16 g_w1h[256 * 768], g_w1l[256 * 768];
__device__ __nv_bfloat16 g_w2h[256 * 192], g_w2l[256 * 192];
__device__ __nv_bfloat16 g_wqh[768 * 256], g_wql[768 * 256];
__device__ __nv_bfloat16 g_wph[256 * 256], g_wpl[256 * 256];
__device__ float g_bqkv[768];
__device__ float g_emb1[(size_t)ROWS_E * EMBD];
__device__ float g_emb2[(size_t)ROWS_E * EMBD];
__device__ float g_z   [(size_t)ROWS_T * EMBD];
__device__ float g_op  [(size_t)ROWS_T * EMBD];

// ---------------- helpers ----------------
__device__ __forceinline__ uint32_t smem_u32(const void* p) {
    return (uint32_t)__cvta_generic_to_shared(p);
}

__device__ __forceinline__ void split2(float x, float y, uint32_t& hi, uint32_t& lo) {
    asm("cvt.rn.bf16x2.f32 %0, %1, %2;" : "=r"(hi) : "f"(y), "f"(x));
    float hx = __uint_as_float(hi << 16);
    float hy = __uint_as_float(hi & 0xffff0000u);
    float lx = x - hx, ly = y - hy;
    asm("cvt.rn.bf16x2.f32 %0, %1, %2;" : "=r"(lo) : "f"(ly), "f"(lx));
}

__device__ __forceinline__ void split1(float v, __nv_bfloat16& hi, __nv_bfloat16& lo) {
    hi = __float2bfloat16(v);
    lo = __float2bfloat16(v - __bfloat162float(hi));
}

__device__ __forceinline__ void mma16816(float* c, const uint32_t* a, const uint32_t* b) {
    asm volatile("mma.sync.aligned.m16n8k16.row.col.f32.bf16.bf16.f32 "
                 "{%0,%1,%2,%3}, {%4,%5,%6,%7}, {%8,%9}, {%0,%1,%2,%3};"
                 : "+f"(c[0]), "+f"(c[1]), "+f"(c[2]), "+f"(c[3])
                 : "r"(a[0]), "r"(a[1]), "r"(a[2]), "r"(a[3]), "r"(b[0]), "r"(b[1]));
}

__device__ __forceinline__ void ldsm4v(uint32_t* r, uint32_t addr) {
    asm volatile("ldmatrix.sync.aligned.m8n8.x4.shared.b16 {%0,%1,%2,%3}, [%4];"
        : "=r"(r[0]), "=r"(r[1]), "=r"(r[2]), "=r"(r[3]) : "r"(addr));
}

__device__ __forceinline__ void ldsm4t(uint32_t* r, uint32_t addr) {
    asm volatile("ldmatrix.sync.aligned.m8n8.x4.trans.shared.b16 {%0,%1,%2,%3}, [%4];"
        : "=r"(r[0]), "=r"(r[1]), "=r"(r[2]), "=r"(r[3]) : "r"(addr));
}

__device__ __forceinline__ void cp16(uint32_t smem, const void* gmem) {
    asm volatile("cp.async.ca.shared.global [%0], [%1], 16;" :: "r"(smem), "l"(gmem));
}
__device__ __forceinline__ void cp_commit() {
    asm volatile("cp.async.commit_group;" ::: "memory");
}
__device__ __forceinline__ void cp_wait1() {
    asm volatile("cp.async.wait_group 1;" ::: "memory");
}
__device__ __forceinline__ void cp_wait0() {
    asm volatile("cp.async.wait_group 0;" ::: "memory");
}

// exp on the FMA pipe; valid for x <= 0
__device__ __forceinline__ float fast_exp(float x) {
    float y = x * 1.4426950408889634f;
    float n = rintf(y);
    float f = y - n;
    float p = 1.3333558146e-3f;
    p = fmaf(p, f, 9.6181291076e-3f);
    p = fmaf(p, f, 5.5504108664e-2f);
    p = fmaf(p, f, 2.4022650696e-1f);
    p = fmaf(p, f, 6.9314718056e-1f);
    p = fmaf(p, f, 1.0f);
    int e = (int)n;
    float r = __int_as_float((uint32_t)(e + 127) << 23) * p;
    return (n < -125.f) ? 0.f : r;
}

__device__ __forceinline__ float block_sum_256(float v, float* sh) {
    #pragma unroll
    for (int o = 16; o > 0; o >>= 1) v += __shfl_xor_sync(0xffffffffu, v, o);
    __syncthreads();
    if ((threadIdx.x & 31) == 0) sh[threadIdx.x >> 5] = v;
    __syncthreads();
    float r = 0.f;
    #pragma unroll
    for (int i = 0; i < 8; i++) r += sh[i];
    return r;
}

// ---------------- merged weight prep (ONE launch) ----------------
// [0,196608)        W1 -> g_w1h/l   (Kd=768)
// [196608,245760)   W2 -> g_w2h/l   (Kd=192)
// [245760,311296)   Wp -> g_wph/l   (Kd=256)
// [311296,507904)   Wq|Wk|Wv -> g_wqh/l (Kd=256) + bias
__global__ void prep_kernel(const float* __restrict__ W1, const float* __restrict__ W2,
                            const float* __restrict__ Wp, const float* __restrict__ Wq,
                            const float* __restrict__ Wk, const float* __restrict__ Wv,
                            const float* __restrict__ bq, const float* __restrict__ bk,
                            const float* __restrict__ bv) {
    int idx = blockIdx.x * 256 + threadIdx.x;
    __nv_bfloat16 h_, l_;
    if (idx < 196608) {
        int n = idx / 768, k = idx % 768;
        split1(W1[k * 256 + n], h_, l_);
        g_w1h[idx] = h_; g_w1l[idx] = l_;
    } else if (idx < 245760) {
        int li = idx - 196608;
        int n = li / 192, k = li % 192;
        split1(W2[k * 256 + n], h_, l_);
        g_w2h[li] = h_; g_w2l[li] = l_;
    } else if (idx < 311296) {
        int li = idx - 245760;
        int n = li >> 8, k = li & 255;
        split1(Wp[k * 256 + n], h_, l_);
        g_wph[li] = h_; g_wpl[li] = l_;
    } else {
        int li = idx - 311296;
        int n = li >> 8, k = li & 255;
        const float* src = (n < 256) ? Wq : ((n < 512) ? Wk : Wv);
        split1(src[k * 256 + (n & 255)], h_, l_);
        g_wqh[li] = h_; g_wql[li] = l_;
        if (li < 768) g_bqkv[li] = ((li < 256) ? bq : ((li < 512) ? bk : bv))[li & 255];
    }
}

// ---------------- merged im2row (ONE launch; writes split bf16) ----------------
#define N_IM1 ((size_t)ROWS_E * K1)   // 19267584
__global__ void im2row_kernel(const float* __restrict__ x) {
    size_t idx = (size_t)blockIdx.x * 256 + threadIdx.x;
    __nv_bfloat16 h_, l_;
    if (idx < N_IM1) {
        int f = (int)(idx % K1);
        int r = (int)(idx / K1);
        int b = r / NP, i = r % NP;
        int hi = i / 14, wi = i % 14;
        int pr = f / 48; int rem = f % 48; int pc = rem / 3; int c = rem % 3;
        float val = x[(((size_t)b * 3 + c) * 224 + (hi * 16 + pr)) * 224 + (wi * 16 + pc)];
        split1(val, h_, l_);
        g_p1h[idx] = h_; g_p1l[idx] = l_;
    } else {
        size_t li = idx - N_IM1;
        int f = (int)(li % K2);
        int r = (int)(li / K2);
        int b = r / NP, j = r % NP;
        int m = 4 * j + 3;
        int hi = m / 28, wi = m % 28;
        int pr = f / 24; int rem = f % 24; int pc = rem / 3; int c = rem % 3;
        float val = x[(((size_t)b * 3 + c) * 224 + (hi * 8 + pr)) * 224 + (wi * 8 + pc)];
        split1(val, h_, l_);
        g_p2h[li] = h_; g_p2l[li] = l_;
    }
}

// ---------------- bf16 tensor-core GEMM, cp.async staged, pre-split ----------------
#define GAP  40
#define GSTG (4 * 128 * GAP)
#define GEMM2_SMEM (2 * GSTG * 2)

__global__ __launch_bounds__(256)
void gemm_mma2(const __nv_bfloat16* __restrict__ Ah, const __nv_bfloat16* __restrict__ Al,
               const __nv_bfloat16* __restrict__ Bh, const __nv_bfloat16* __restrict__ Bl,
               const float* __restrict__ bias, float* __restrict__ C,
               __nv_bfloat16* __restrict__ Ch, __nv_bfloat16* __restrict__ Cl,
               int M, int N, int K) {
    extern __shared__ __nv_bfloat16 gsm[];
    uint32_t sbase = smem_u32(gsm);
    int t = threadIdx.x, lane = t & 31, w = t >> 5;
    int g = lane >> 2, tig = lane & 3;
    int wm = (w & 1) * 64, wn = (w >> 1) * 32;
    int m0 = blockIdx.y * 128, n0 = blockIdx.x * 128;
    const __nv_bfloat16* Abh = Ah + (size_t)m0 * K;
    const __nv_bfloat16* Abl = Al + (size_t)m0 * K;
    const __nv_bfloat16* Bbh = Bh + (size_t)n0 * K;
    const __nv_bfloat16* Bbl = Bl + (size_t)n0 * K;

    int a_row = (lane & 7) + ((lane >> 3) & 1) * 8;
    int a_col = ((lane >> 4) & 1) * 8;
    int b_row = (lane & 7) + ((lane >> 4) & 1) * 8;
    int b_col = ((lane >> 3) & 1) * 8;

    auto load_stage = [&](int tt, int stg) {
        int kb = tt * 32;
        uint32_t dst = sbase + stg * GSTG * 2;
        #pragma unroll
        for (int j = 0; j < 2; j++) {
            int i = t + 256 * j;
            int r = i >> 2, c8 = (i & 3) * 8;
            cp16(dst + (r * GAP + c8) * 2,                 Abh + (size_t)r * K + kb + c8);
            cp16(dst + (128 * GAP + r * GAP + c8) * 2,     Abl + (size_t)r * K + kb + c8);
            cp16(dst + (2 * 128 * GAP + r * GAP + c8) * 2, Bbh + (size_t)r * K + kb + c8);
            cp16(dst + (3 * 128 * GAP + r * GAP + c8) * 2, Bbl + (size_t)r * K + kb + c8);
        }
    };

    load_stage(0, 0);
    cp_commit();

    float acc[4][4][4];
    #pragma unroll
    for (int mt = 0; mt < 4; mt++)
        #pragma unroll
        for (int nf = 0; nf < 4; nf++)
            #pragma unroll
            for (int e = 0; e < 4; e++) acc[mt][nf][e] = 0.f;

    int kt = K >> 5;
    for (int tt = 0; tt < kt; tt++) {
        int cur = tt & 1;
        if (tt + 1 < kt) {
            load_stage(tt + 1, cur ^ 1);
            cp_commit();
            cp_wait1();
        } else {
            cp_wait0();
        }
        __syncthreads();

        uint32_t sA = sbase + cur * GSTG * 2;
        #pragma unroll
        for (int ks = 0; ks < 32; ks += 16) {
            uint32_t ah4[4][4], al4[4][4];
            #pragma unroll
            for (int mt = 0; mt < 4; mt++) {
                uint32_t ad = sA + ((wm + mt * 16 + a_row) * GAP + ks + a_col) * 2;
                ldsm4v(ah4[mt], ad);
                ldsm4v(al4[mt], ad + 128 * GAP * 2);
            }
            uint32_t bh4[2][4], bl4[2][4];
            #pragma unroll
            for (int nt2 = 0; nt2 < 2; nt2++) {
                uint32_t bd = sA + (2 * 128 * GAP + (wn + nt2 * 16 + b_row) * GAP + ks + b_col) * 2;
                ldsm4v(bh4[nt2], bd);
                ldsm4v(bl4[nt2], bd + 128 * GAP * 2);
            }
            #pragma unroll
            for (int mt = 0; mt < 4; mt++)
                #pragma unroll
                for (int nf = 0; nf < 4; nf++) {
                    uint32_t* bhp = &bh4[nf >> 1][(nf & 1) * 2];
                    uint32_t* blp = &bl4[nf >> 1][(nf & 1) * 2];
                    mma16816(acc[mt][nf], ah4[mt], bhp);
                    mma16816(acc[mt][nf], ah4[mt], blp);
                    mma16816(acc[mt][nf], al4[mt], bhp);
                }
        }
        __syncthreads();
    }

    #pragma unroll
    for (int mt = 0; mt < 4; mt++) {
        int r0 = m0 + wm + mt * 16 + g;
        #pragma unroll
        for (int nf = 0; nf < 4; nf++) {
            int c0 = n0 + wn + nf * 8 + 2 * tig;
            float2 v0, v1;
            v0.x = acc[mt][nf][0]; v0.y = acc[mt][nf][1];
            v1.x = acc[mt][nf][2]; v1.y = acc[mt][nf][3];
            if (bias) {
                float2 bb = *(const float2*)(bias + c0);
                v0.x += bb.x; v0.y += bb.y;
                v1.x += bb.x; v1.y += bb.y;
            }
            if (Ch) {
                uint32_t hh_, ll_;
                split2(v0.x, v0.y, hh_, ll_);
                *(uint32_t*)&Ch[(size_t)r0 * N + c0] = hh_;
                *(uint32_t*)&Cl[(size_t)r0 * N + c0] = ll_;
                split2(v1.x, v1.y, hh_, ll_);
                *(uint32_t*)&Ch[(size_t)(r0 + 8) * N + c0] = hh_;
                *(uint32_t*)&Cl[(size_t)(r0 + 8) * N + c0] = ll_;
            } else {
                *(float2*)(C + (size_t)r0 * N + c0) = v0;
                *(float2*)(C + (size_t)(r0 + 8) * N + c0) = v1;
            }
        }
    }
}

// ---------------- fused assemble + LN1 ----------------
__global__ void ln_fused_kernel(const float* __restrict__ gw, const float* __restrict__ bw,
                                const float* __restrict__ b1, const float* __restrict__ cls1,
                                const float* __restrict__ b2, const float* __restrict__ cls2) {
    int wid = threadIdx.x >> 5, lane = threadIdx.x & 31;
    long long row = (long long)blockIdx.x * 8 + wid;
    if (row >= ROWS_T) return;
    int b = (int)(row / NTOK), n = (int)(row % NTOK);

    const float* src; const float* badd = nullptr;
    if (n == 0)           { src = cls2; }
    else if (n <= NP)     { src = g_emb2 + ((size_t)(b * NP + (n - 1))) * EMBD; badd = b2; }
    else if (n == NP + 1) { src = cls1; }
    else                  { src = g_emb1 + ((size_t)(b * NP + (n - NP - 2))) * EMBD; badd = b1; }

    float v[8];
    float s = 0.f;
    #pragma unroll
    for (int j = 0; j < 8; j++) {
        int c = lane + 32 * j;
        v[j] = src[c] + (badd ? badd[c] : 0.f);
        s += v[j];
    }
    #pragma unroll
    for (int o = 16; o > 0; o >>= 1) s += __shfl_xor_sync(0xffffffffu, s, o);
    float mean = s * (1.f / EMBD);
    float s2 = 0.f;
    #pragma unroll
    for (int j = 0; j < 8; j++) { float d = v[j] - mean; s2 += d * d; }
    #pragma unroll
    for (int o = 16; o > 0; o >>= 1) s2 += __shfl_xor_sync(0xffffffffu, s2, o);
    float inv = rsqrtf(s2 * (1.f / EMBD) + 1e-5f);
    #pragma unroll
    for (int j = 0; j < 8; j++) {
        int c = lane + 32 * j;
        g_z[row * EMBD + c] = v[j];
        float o = (v[j] - mean) * inv * gw[c] + bw[c];
        __nv_bfloat16 h_, l_;
        split1(o, h_, l_);
        g_hh[row * EMBD + c] = h_;
        g_hl[row * EMBD + c] = l_;
    }
}

// z += LN(op)
__global__ void ln_res_kernel(const float* __restrict__ gw, const float* __restrict__ bw) {
    int wid = threadIdx.x >> 5, lane = threadIdx.x & 31;
    long long row = (long long)blockIdx.x * 8 + wid;
    if (row >= ROWS_T) return;
    const float* p = g_op + row * EMBD;
    float v[8];
    float s = 0.f;
    #pragma unroll
    for (int j = 0; j < 8; j++) { v[j] = p[lane + 32 * j]; s += v[j]; }
    #pragma unroll
    for (int o = 16; o > 0; o >>= 1) s += __shfl_xor_sync(0xffffffffu, s, o);
    float mean = s * (1.f / EMBD);
    float s2 = 0.f;
    #pragma unroll
    for (int j = 0; j < 8; j++) { float d = v[j] - mean; s2 += d * d; }
    #pragma unroll
    for (int o = 16; o > 0; o >>= 1) s2 += __shfl_xor_sync(0xffffffffu, s2, o);
    float inv = rsqrtf(s2 * (1.f / EMBD) + 1e-5f);
    #pragma unroll
    for (int j = 0; j < 8; j++) {
        int c = lane + 32 * j;
        g_z[row * EMBD + c] += (v[j] - mean) * inv * gw[c] + bw[c];
    }
}

// ---------------- tensor-core flash attention v4 ----------------
// BM=128 (8 warps, 256 threads), KV chunks of 64, cp.async double-buffered.
#define FP 136
#define KVSTG (4 * 64 * FP)                         // one K/V stage (Kh,Kl,Vh,Vl)
#define FA4_SMEM ((2 * 128 * FP + 2 * KVSTG) * 2)   // 208896 bytes

__global__ __launch_bounds__(256)
void flash4_kernel() {
    extern __shared__ __nv_bfloat16 fsm4[];
    uint32_t sbase = smem_u32(fsm4);

    int tid = threadIdx.x;
    int lane = tid & 31, w = tid >> 5;
    int g = lane >> 2, tig = lane & 3;
    int m0 = blockIdx.x * 128;
    int b = blockIdx.y >> 1, h = blockIdx.y & 1;

    size_t rowbase = (size_t)b * NTOK * 768;
    const __nv_bfloat16* qh_g = g_qkvh + rowbase + h * DH;
    const __nv_bfloat16* ql_g = g_qkvl + rowbase + h * DH;
    const __nv_bfloat16* kh_g = qh_g + 256;
    const __nv_bfloat16* kl_g = ql_g + 256;
    const __nv_bfloat16* vh_g = qh_g + 512;
    const __nv_bfloat16* vl_g = ql_g + 512;

    uint32_t Qh_s = sbase;
    uint32_t Ql_s = sbase + 128 * FP * 2;
    uint32_t KV_s = sbase + 2 * 128 * FP * 2;

    for (int i = tid; i < 2048; i += 256) {
        int r = i >> 4, c8 = (i & 15) * 8;
        int src = m0 + r; if (src > NTOK - 1) src = NTOK - 1;
        cp16(Qh_s + (r * FP + c8) * 2, qh_g + (size_t)src * 768 + c8);
        cp16(Ql_s + (r * FP + c8) * 2, ql_g + (size_t)src * 768 + c8);
    }
    for (int i = tid; i < 1024; i += 256) {
        int r = i >> 4, c8 = (i & 15) * 8;
        int src = r; if (src > NTOK - 1) src = NTOK - 1;
        cp16(KV_s + (r * FP + c8) * 2,               kh_g + (size_t)src * 768 + c8);
        cp16(KV_s + (64 * FP + r * FP + c8) * 2,     kl_g + (size_t)src * 768 + c8);
        cp16(KV_s + (2 * 64 * FP + r * FP + c8) * 2, vh_g + (size_t)src * 768 + c8);
        cp16(KV_s + (3 * 64 * FP + r * FP + c8) * 2, vl_g + (size_t)src * 768 + c8);
    }
    cp_commit();

    float oacc[16][4];
    #pragma unroll
    for (int i = 0; i < 16; i++)
        #pragma unroll
        for (int e = 0; e < 4; e++) oacc[i][e] = 0.f;
    float rm0 = -1e30f, rm1 = -1e30f, rl0 = 0.f, rl1 = 0.f;

    int a_row = (lane & 7) + ((lane >> 3) & 1) * 8;
    int a_col = ((lane >> 4) & 1) * 8;
    int b_row = (lane & 7) + ((lane >> 4) & 1) * 8;
    int b_col = ((lane >> 3) & 1) * 8;

    for (int nt = 0; nt < 7; nt++) {
        if (nt < 6) {
            int n0n = (nt + 1) * 64;
            uint32_t stn = KV_s + ((nt + 1) & 1) * KVSTG * 2;
            for (int i = tid; i < 1024; i += 256) {
                int r = i >> 4, c8 = (i & 15) * 8;
                int src = n0n + r; if (src > NTOK - 1) src = NTOK - 1;
                cp16(stn + (r * FP + c8) * 2,               kh_g + (size_t)src * 768 + c8);
                cp16(stn + (64 * FP + r * FP + c8) * 2,     kl_g + (size_t)src * 768 + c8);
                cp16(stn + (2 * 64 * FP + r * FP + c8) * 2, vh_g + (size_t)src * 768 + c8);
                cp16(stn + (3 * 64 * FP + r * FP + c8) * 2, vl_g + (size_t)src * 768 + c8);
            }
            cp_commit();
            cp_wait1();
        } else {
            cp_wait0();
        }
        __syncthreads();

        int n0c = nt * 64;
        uint32_t stc = KV_s + (nt & 1) * KVSTG * 2;

        // S = Q K^T (3-pass split)
        float sacc[8][4];
        #pragma unroll
        for (int nf = 0; nf < 8; nf++)
            #pragma unroll
            for (int e = 0; e < 4; e++) sacc[nf][e] = 0.f;

        #pragma unroll
        for (int ks = 0; ks < 8; ks++) {
            int k0 = ks * 16;
            uint32_t ah[4], al[4];
            uint32_t qad = Qh_s + ((w * 16 + a_row) * FP + k0 + a_col) * 2;
            ldsm4v(ah, qad);
            ldsm4v(al, qad + 128 * FP * 2);
            #pragma unroll
            for (int nt2 = 0; nt2 < 4; nt2++) {
                uint32_t kad = stc + ((nt2 * 16 + b_row) * FP + k0 + b_col) * 2;
                uint32_t bh_[4], bl_[4];
                ldsm4v(bh_, kad);
                ldsm4v(bl_, kad + 64 * FP * 2);
                mma16816(sacc[nt2 * 2],     ah, &bh_[0]);
                mma16816(sacc[nt2 * 2],     ah, &bl_[0]);
                mma16816(sacc[nt2 * 2],     al, &bh_[0]);
                mma16816(sacc[nt2 * 2 + 1], ah, &bh_[2]);
                mma16816(sacc[nt2 * 2 + 1], ah, &bl_[2]);
                mma16816(sacc[nt2 * 2 + 1], al, &bh_[2]);
            }
        }

        // mask + online softmax
        float mx0 = -1e30f, mx1 = -1e30f;
        #pragma unroll
        for (int nf = 0; nf < 8; nf++) {
            int c0 = n0c + nf * 8 + 2 * tig;
            if (c0 >= NTOK)     { sacc[nf][0] = -1e30f; sacc[nf][2] = -1e30f; }
            if (c0 + 1 >= NTOK) { sacc[nf][1] = -1e30f; sacc[nf][3] = -1e30f; }
            mx0 = fmaxf(mx0, fmaxf(sacc[nf][0], sacc[nf][1]));
            mx1 = fmaxf(mx1, fmaxf(sacc[nf][2], sacc[nf][3]));
        }
        mx0 = fmaxf(mx0, __shfl_xor_sync(0xffffffffu, mx0, 1));
        mx0 = fmaxf(mx0, __shfl_xor_sync(0xffffffffu, mx0, 2));
        mx1 = fmaxf(mx1, __shfl_xor_sync(0xffffffffu, mx1, 1));
        mx1 = fmaxf(mx1, __shfl_xor_sync(0xffffffffu, mx1, 2));
        float nm0 = fmaxf(rm0, mx0), nm1 = fmaxf(rm1, mx1);
        float sc0 = fast_exp(rm0 - nm0), sc1 = fast_exp(rm1 - nm1);
        rm0 = nm0; rm1 = nm1;
        float rs0 = 0.f, rs1 = 0.f;
        uint32_t ph[8][2], pl[8][2];
        #pragma unroll
        for (int nf = 0; nf < 8; nf++) {
            float p0 = fast_exp(sacc[nf][0] - nm0);
            float p1 = fast_exp(sacc[nf][1] - nm0);
            float p2 = fast_exp(sacc[nf][2] - nm1);
            float p3 = fast_exp(sacc[nf][3] - nm1);
            rs0 += p0 + p1; rs1 += p2 + p3;
            split2(p0, p1, ph[nf][0], pl[nf][0]);
            split2(p2, p3, ph[nf][1], pl[nf][1]);
        }
        rs0 += __shfl_xor_sync(0xffffffffu, rs0, 1);
        rs0 += __shfl_xor_sync(0xffffffffu, rs0, 2);
        rs1 += __shfl_xor_sync(0xffffffffu, rs1, 1);
        rs1 += __shfl_xor_sync(0xffffffffu, rs1, 2);
        rl0 = rl0 * sc0 + rs0;
        rl1 = rl1 * sc1 + rs1;
        #pragma unroll
        for (int onf = 0; onf < 16; onf++) {
            oacc[onf][0] *= sc0; oacc[onf][1] *= sc0;
            oacc[onf][2] *= sc1; oacc[onf][3] *= sc1;
        }

        // O += P V
        uint32_t vbase = stc + 2 * 64 * FP * 2;
        #pragma unroll
        for (int ks = 0; ks < 4; ks++) {
            uint32_t ah[4] = {ph[2 * ks][0], ph[2 * ks][1], ph[2 * ks + 1][0], ph[2 * ks + 1][1]};
            uint32_t al[4] = {pl[2 * ks][0], pl[2 * ks][1], pl[2 * ks + 1][0], pl[2 * ks + 1][1]};
            #pragma unroll
            for (int dt = 0; dt < 8; dt++) {
                uint32_t vad = vbase + ((ks * 16 + a_row) * FP + dt * 16 + a_col) * 2;
                uint32_t bh_[4], bl_[4];
                ldsm4t(bh_, vad);
                ldsm4t(bl_, vad + 64 * FP * 2);
                mma16816(oacc[dt * 2],     ah, &bh_[0]);
                mma16816(oacc[dt * 2],     ah, &bl_[0]);
                mma16816(oacc[dt * 2],     al, &bh_[0]);
                mma16816(oacc[dt * 2 + 1], ah, &bh_[2]);
                mma16816(oacc[dt * 2 + 1], ah, &bl_[2]);
                mma16816(oacc[dt * 2 + 1], al, &bh_[2]);
            }
        }
        __syncthreads();
    }

    // epilogue
    float inv0 = 1.f / (rl0 * 16.f);
    float inv1 = 1.f / (rl1 * 16.f);
    int row0 = m0 + w * 16 + g, row1 = row0 + 8;
    #pragma unroll
    for (int onf = 0; onf < 16; onf++) {
        int col = h * DH + onf * 8 + 2 * tig;
        uint32_t hi, lo;
        if (row0 < NTOK) {
            split2(oacc[onf][0] * inv0, oacc[onf][1] * inv0, hi, lo);
            size_t off = ((size_t)b * NTOK + row0) * EMBD + col;
            *(uint32_t*)&g_oh[off] = hi;
            *(uint32_t*)&g_ol[off] = lo;
        }
        if (row1 < NTOK) {
            split2(oacc[onf][2] * inv1, oacc[onf][3] * inv1, hi, lo);
            size_t off = ((size_t)b * NTOK + row1) * EMBD + col;
            *(uint32_t*)&g_oh[off] = hi;
            *(uint32_t*)&g_ol[off] = lo;
        }
    }
}

// ---------------- head ----------------
__global__ void head_kernel(const float* __restrict__ lg, const float* __restrict__ lb,
                            const float* __restrict__ Wc, const float* __restrict__ bc,
                            float* __restrict__ out) {
    __shared__ float sh[8];
    int b = blockIdx.x;
    int c = threadIdx.x;
    const float* zb = g_z + (size_t)b * NTOK * EMBD;
    float s = 0.f;
    #pragma unroll 8
    for (int n = 0; n < NTOK; n++) s += zb[(size_t)n * EMBD + c];
    float pooled = s * (1.f / NTOK);
    float mean = block_sum_256(pooled, sh) * (1.f / EMBD);
    float d = pooled - mean;
    float var = block_sum_256(d * d, sh) * (1.f / EMBD);
    float ln = d * rsqrtf(var + 1e-5f) * lg[c] + lb[c];
    float l0 = block_sum_256(ln * Wc[c * 2 + 0], sh);
    float l1 = block_sum_256(ln * Wc[c * 2 + 1], sh);
    if (c == 0) {
        l0 += bc[0];
        l1 += bc[1];
        float mx = fmaxf(l0, l1);
        float lse = mx + logf(expf(l0 - mx) + expf(l1 - mx));
        out[b * 2 + 0] = l0 - lse;
        out[b * 2 + 1] = l1 - lse;
    }
}

// ---------------- launch ----------------
extern "C" void kernel_launch(void* const* d_in, const int* in_sizes, int n_in,
                              void* d_out, int out_size) {
    const float* x    = (const float*)d_in[0];
    const float* W1   = (const float*)d_in[1];
    const float* b1   = (const float*)d_in[2];
    const float* cls1 = (const float*)d_in[3];
    const float* W2   = (const float*)d_in[4];
    const float* b2   = (const float*)d_in[5];
    const float* cls2 = (const float*)d_in[6];
    const float* ln1g = (const float*)d_in[7];
    const float* ln1b = (const float*)d_in[8];
    const float* Wq   = (const float*)d_in[9];
    const float* bq   = (const float*)d_in[10];
    const float* Wk   = (const float*)d_in[11];
    const float* bk   = (const float*)d_in[12];
    const float* Wv   = (const float*)d_in[13];
    const float* bv   = (const float*)d_in[14];
    const float* Wp   = (const float*)d_in[15];
    const float* bp   = (const float*)d_in[16];
    const float* ln2g = (const float*)d_in[17];
    const float* ln2b = (const float*)d_in[18];
    const float* lncg = (const float*)d_in[19];
    const float* lncb = (const float*)d_in[20];
    const float* Wc   = (const float*)d_in[21];
    const float* bc   = (const float*)d_in[22];
    float* out = (float*)d_out;

    __nv_bfloat16 *p1h, *p1l, *p2h, *p2l, *hh, *hl, *oh, *ol, *qh, *ql;
    __nv_bfloat16 *w1h, *w1l, *w2h, *w2l, *wqh, *wql, *wph, *wpl;
    float *e1, *e2, *op_, *bqkv;
    cudaGetSymbolAddress((void**)&p1h, g_p1h);
    cudaGetSymbolAddress((void**)&p1l, g_p1l);
    cudaGetSymbolAddress((void**)&p2h, g_p2h);
    cudaGetSymbolAddress((void**)&p2l, g_p2l);
    cudaGetSymbolAddress((void**)&hh, g_hh);
    cudaGetSymbolAddress((void**)&hl, g_hl);
    cudaGetSymbolAddress((void**)&oh, g_oh);
    cudaGetSymbolAddress((void**)&ol, g_ol);
    cudaGetSymbolAddress((void**)&qh, g_qkvh);
    cudaGetSymbolAddress((void**)&ql, g_qkvl);
    cudaGetSymbolAddress((void**)&w1h, g_w1h);
    cudaGetSymbolAddress((void**)&w1l, g_w1l);
    cudaGetSymbolAddress((void**)&w2h, g_w2h);
    cudaGetSymbolAddress((void**)&w2l, g_w2l);
    cudaGetSymbolAddress((void**)&wqh, g_wqh);
    cudaGetSymbolAddress((void**)&wql, g_wql);
    cudaGetSymbolAddress((void**)&wph, g_wph);
    cudaGetSymbolAddress((void**)&wpl, g_wpl);
    cudaGetSymbolAddress((void**)&e1, g_emb1);
    cudaGetSymbolAddress((void**)&e2, g_emb2);
    cudaGetSymbolAddress((void**)&op_, g_op);
    cudaGetSymbolAddress((void**)&bqkv, g_bqkv);

    cudaFuncSetAttribute(gemm_mma2, cudaFuncAttributeMaxDynamicSharedMemorySize, GEMM2_SMEM);
    cudaFuncSetAttribute(flash4_kernel, cudaFuncAttributeMaxDynamicSharedMemorySize, FA4_SMEM);

    // launch 0: merged weight prep
    prep_kernel<<<(507904 + 255) / 256, 256>>>(W1, W2, Wp, Wq, Wk, Wv, bq, bk, bv);
    // launch 1: merged im2row
    im2row_kernel<<<(int)((N_IM1 + (size_t)ROWS_E * K2) / 256), 256>>>(x);

    // launches 2,3: patch embeds -> fp32
    gemm_mma2<<<dim3(2, ROWS_E / 128), 256, GEMM2_SMEM>>>(p1h, p1l, w1h, w1l, nullptr, e1, nullptr, nullptr, ROWS_E, EMBD, K1);
    gemm_mma2<<<dim3(2, ROWS_E / 128), 256, GEMM2_SMEM>>>(p2h, p2l, w2h, w2l, nullptr, e2, nullptr, nullptr, ROWS_E, EMBD, K2);

    // launch 4: fused assemble + LN1
    ln_fused_kernel<<<ROWS_T / 8, 256>>>(ln1g, ln1b, b1, cls1, b2, cls2);

    // launch 5: fused QKV -> split bf16   (ncu -s 5 lands here)
    gemm_mma2<<<dim3(6, ROWS_T / 128), 256, GEMM2_SMEM>>>(hh, hl, wqh, wql, bqkv, nullptr, qh, ql, ROWS_T, 768, EMBD);

    // launch 6: flash attention (BM=128)
    flash4_kernel<<<dim3(4, BATCH * HEADS), 256, FA4_SMEM>>>();

    // launch 7: output projection -> fp32
    gemm_mma2<<<dim3(2, ROWS_T / 128), 256, GEMM2_SMEM>>>(oh, ol, wph, wpl, bp, op_, nullptr, nullptr, ROWS_T, EMBD, EMBD);

    // launches 8,9
    ln_res_kernel<<<ROWS_T / 8, 256>>>(ln2g, ln2b);
    head_kernel<<<BATCH, 256>>>(lncg, lncb, Wc, bc, out);
}

// round 15
// speedup vs baseline: 1.0862x; 1.0862x over previous
#include <cuda_runtime.h>
#include <cuda_bf16.h>
#include <cstdint>
#include <math.h>

// ---------------- problem constants ----------------
#define BATCH   128
#define NTOK    394
#define EMBD    256
#define NP      196
#define HEADS   2
#define DH      128
#define K1      768
#define K2      192
#define ROWS_E  (BATCH*NP)         // 25088
#define ROWS_T  (BATCH*NTOK)       // 50432

// ---------------- scratch ----------------
__device__ __nv_bfloat16 g_p1h[(size_t)ROWS_E * K1];
__device__ __nv_bfloat16 g_p1l[(size_t)ROWS_E * K1];
__device__ __nv_bfloat16 g_p2h[(size_t)ROWS_E * K2];
__device__ __nv_bfloat16 g_p2l[(size_t)ROWS_E * K2];
__device__ __nv_bfloat16 g_hh [(size_t)ROWS_T * EMBD];
__device__ __nv_bfloat16 g_hl [(size_t)ROWS_T * EMBD];
__device__ __nv_bfloat16 g_oh [(size_t)ROWS_T * EMBD];
__device__ __nv_bfloat16 g_ol [(size_t)ROWS_T * EMBD];
__device__ __nv_bfloat16 g_qkvh[(size_t)ROWS_T * 768];
__device__ __nv_bfloat16 g_qkvl[(size_t)ROWS_T * 768];
__device__ __nv_bfloat16 g_w1h[256 * 768], g_w1l[256 * 768];
__device__ __nv_bfloat16 g_w2h[256 * 192], g_w2l[256 * 192];
__device__ __nv_bfloat16 g_wqh[768 * 256], g_wql[768 * 256];
__device__ __nv_bfloat16 g_wph[256 * 256], g_wpl[256 * 256];
__device__ float g_bqkv[768];
__device__ float g_emb1[(size_t)ROWS_E * EMBD];
__device__ float g_emb2[(size_t)ROWS_E * EMBD];
__device__ float g_z   [(size_t)ROWS_T * EMBD];
__device__ float g_op  [(size_t)ROWS_T * EMBD];

// ---------------- helpers ----------------
__device__ __forceinline__ uint32_t smem_u32(const void* p) {
    return (uint32_t)__cvta_generic_to_shared(p);
}

__device__ __forceinline__ void split2(float x, float y, uint32_t& hi, uint32_t& lo) {
    asm("cvt.rn.bf16x2.f32 %0, %1, %2;" : "=r"(hi) : "f"(y), "f"(x));
    float hx = __uint_as_float(hi << 16);
    float hy = __uint_as_float(hi & 0xffff0000u);
    float lx = x - hx, ly = y - hy;
    asm("cvt.rn.bf16x2.f32 %0, %1, %2;" : "=r"(lo) : "f"(ly), "f"(lx));
}

__device__ __forceinline__ void split1(float v, __nv_bfloat16& hi, __nv_bfloat16& lo) {
    hi = __float2bfloat16(v);
    lo = __float2bfloat16(v - __bfloat162float(hi));
}

__device__ __forceinline__ void mma16816(float* c, const uint32_t* a, const uint32_t* b) {
    asm volatile("mma.sync.aligned.m16n8k16.row.col.f32.bf16.bf16.f32 "
                 "{%0,%1,%2,%3}, {%4,%5,%6,%7}, {%8,%9}, {%0,%1,%2,%3};"
                 : "+f"(c[0]), "+f"(c[1]), "+f"(c[2]), "+f"(c[3])
                 : "r"(a[0]), "r"(a[1]), "r"(a[2]), "r"(a[3]), "r"(b[0]), "r"(b[1]));
}

__device__ __forceinline__ void ldsm4v(uint32_t* r, uint32_t addr) {
    asm volatile("ldmatrix.sync.aligned.m8n8.x4.shared.b16 {%0,%1,%2,%3}, [%4];"
        : "=r"(r[0]), "=r"(r[1]), "=r"(r[2]), "=r"(r[3]) : "r"(addr));
}

__device__ __forceinline__ void ldsm4t(uint32_t* r, uint32_t addr) {
    asm volatile("ldmatrix.sync.aligned.m8n8.x4.trans.shared.b16 {%0,%1,%2,%3}, [%4];"
        : "=r"(r[0]), "=r"(r[1]), "=r"(r[2]), "=r"(r[3]) : "r"(addr));
}

__device__ __forceinline__ void cp16(uint32_t smem, const void* gmem) {
    asm volatile("cp.async.ca.shared.global [%0], [%1], 16;" :: "r"(smem), "l"(gmem));
}
__device__ __forceinline__ void cp_commit() {
    asm volatile("cp.async.commit_group;" ::: "memory");
}
__device__ __forceinline__ void cp_wait1() {
    asm volatile("cp.async.wait_group 1;" ::: "memory");
}
__device__ __forceinline__ void cp_wait0() {
    asm volatile("cp.async.wait_group 0;" ::: "memory");
}

// exp on the FMA pipe; valid for x <= 0
__device__ __forceinline__ float fast_exp(float x) {
    float y = x * 1.4426950408889634f;
    float n = rintf(y);
    float f = y - n;
    float p = 1.3333558146e-3f;
    p = fmaf(p, f, 9.6181291076e-3f);
    p = fmaf(p, f, 5.5504108664e-2f);
    p = fmaf(p, f, 2.4022650696e-1f);
    p = fmaf(p, f, 6.9314718056e-1f);
    p = fmaf(p, f, 1.0f);
    int e = (int)n;
    float r = __int_as_float((uint32_t)(e + 127) << 23) * p;
    return (n < -125.f) ? 0.f : r;
}

__device__ __forceinline__ float block_sum_256(float v, float* sh) {
    #pragma unroll
    for (int o = 16; o > 0; o >>= 1) v += __shfl_xor_sync(0xffffffffu, v, o);
    __syncthreads();
    if ((threadIdx.x & 31) == 0) sh[threadIdx.x >> 5] = v;
    __syncthreads();
    float r = 0.f;
    #pragma unroll
    for (int i = 0; i < 8; i++) r += sh[i];
    return r;
}

// ---------------- merged weight prep (ONE launch) ----------------
__global__ void prep_kernel(const float* __restrict__ W1, const float* __restrict__ W2,
                            const float* __restrict__ Wp, const float* __restrict__ Wq,
                            const float* __restrict__ Wk, const float* __restrict__ Wv,
                            const float* __restrict__ bq, const float* __restrict__ bk,
                            const float* __restrict__ bv) {
    int idx = blockIdx.x * 256 + threadIdx.x;
    __nv_bfloat16 h_, l_;
    if (idx < 196608) {
        int n = idx / 768, k = idx % 768;
        split1(W1[k * 256 + n], h_, l_);
        g_w1h[idx] = h_; g_w1l[idx] = l_;
    } else if (idx < 245760) {
        int li = idx - 196608;
        int n = li / 192, k = li % 192;
        split1(W2[k * 256 + n], h_, l_);
        g_w2h[li] = h_; g_w2l[li] = l_;
    } else if (idx < 311296) {
        int li = idx - 245760;
        int n = li >> 8, k = li & 255;
        split1(Wp[k * 256 + n], h_, l_);
        g_wph[li] = h_; g_wpl[li] = l_;
    } else {
        int li = idx - 311296;
        int n = li >> 8, k = li & 255;
        const float* src = (n < 256) ? Wq : ((n < 512) ? Wk : Wv);
        split1(src[k * 256 + (n & 255)], h_, l_);
        g_wqh[li] = h_; g_wql[li] = l_;
        if (li < 768) g_bqkv[li] = ((li < 256) ? bq : ((li < 512) ? bk : bv))[li & 255];
    }
}

// ---------------- merged im2row (ONE launch; writes split bf16) ----------------
#define N_IM1 ((size_t)ROWS_E * K1)   // 19267584
__global__ void im2row_kernel(const float* __restrict__ x) {
    size_t idx = (size_t)blockIdx.x * 256 + threadIdx.x;
    __nv_bfloat16 h_, l_;
    if (idx < N_IM1) {
        int f = (int)(idx % K1);
        int r = (int)(idx / K1);
        int b = r / NP, i = r % NP;
        int hi = i / 14, wi = i % 14;
        int pr = f / 48; int rem = f % 48; int pc = rem / 3; int c = rem % 3;
        float val = x[(((size_t)b * 3 + c) * 224 + (hi * 16 + pr)) * 224 + (wi * 16 + pc)];
        split1(val, h_, l_);
        g_p1h[idx] = h_; g_p1l[idx] = l_;
    } else {
        size_t li = idx - N_IM1;
        int f = (int)(li % K2);
        int r = (int)(li / K2);
        int b = r / NP, j = r % NP;
        int m = 4 * j + 3;
        int hi = m / 28, wi = m % 28;
        int pr = f / 24; int rem = f % 24; int pc = rem / 3; int c = rem % 3;
        float val = x[(((size_t)b * 3 + c) * 224 + (hi * 8 + pr)) * 224 + (wi * 8 + pc)];
        split1(val, h_, l_);
        g_p2h[li] = h_; g_p2l[li] = l_;
    }
}

// ---------------- bf16 tensor-core GEMM, cp.async staged, 2 blocks/SM ----------------
#define GAP  40
#define GSTG (4 * 128 * GAP)
#define GEMM2_SMEM (2 * GSTG * 2)

__global__ __launch_bounds__(256, 2)
void gemm_mma2(const __nv_bfloat16* __restrict__ Ah, const __nv_bfloat16* __restrict__ Al,
               const __nv_bfloat16* __restrict__ Bh, const __nv_bfloat16* __restrict__ Bl,
               const float* __restrict__ bias, float* __restrict__ C,
               __nv_bfloat16* __restrict__ Ch, __nv_bfloat16* __restrict__ Cl,
               int M, int N, int K) {
    extern __shared__ __nv_bfloat16 gsm[];
    uint32_t sbase = smem_u32(gsm);
    int t = threadIdx.x, lane = t & 31, w = t >> 5;
    int g = lane >> 2, tig = lane & 3;
    int wm = (w & 1) * 64, wn = (w >> 1) * 32;
    int m0 = blockIdx.y * 128, n0 = blockIdx.x * 128;
    const __nv_bfloat16* Abh = Ah + (size_t)m0 * K;
    const __nv_bfloat16* Abl = Al + (size_t)m0 * K;
    const __nv_bfloat16* Bbh = Bh + (size_t)n0 * K;
    const __nv_bfloat16* Bbl = Bl + (size_t)n0 * K;

    int a_row = (lane & 7) + ((lane >> 3) & 1) * 8;
    int a_col = ((lane >> 4) & 1) * 8;
    int b_row = (lane & 7) + ((lane >> 4) & 1) * 8;
    int b_col = ((lane >> 3) & 1) * 8;

    auto load_stage = [&](int tt, int stg) {
        int kb = tt * 32;
        uint32_t dst = sbase + stg * GSTG * 2;
        #pragma unroll
        for (int j = 0; j < 2; j++) {
            int i = t + 256 * j;
            int r = i >> 2, c8 = (i & 3) * 8;
            cp16(dst + (r * GAP + c8) * 2,                 Abh + (size_t)r * K + kb + c8);
            cp16(dst + (128 * GAP + r * GAP + c8) * 2,     Abl + (size_t)r * K + kb + c8);
            cp16(dst + (2 * 128 * GAP + r * GAP + c8) * 2, Bbh + (size_t)r * K + kb + c8);
            cp16(dst + (3 * 128 * GAP + r * GAP + c8) * 2, Bbl + (size_t)r * K + kb + c8);
        }
    };

    load_stage(0, 0);
    cp_commit();

    float acc[4][4][4];
    #pragma unroll
    for (int mt = 0; mt < 4; mt++)
        #pragma unroll
        for (int nf = 0; nf < 4; nf++)
            #pragma unroll
            for (int e = 0; e < 4; e++) acc[mt][nf][e] = 0.f;

    int kt = K >> 5;
    for (int tt = 0; tt < kt; tt++) {
        int cur = tt & 1;
        if (tt + 1 < kt) {
            load_stage(tt + 1, cur ^ 1);
            cp_commit();
            cp_wait1();
        } else {
            cp_wait0();
        }
        __syncthreads();

        uint32_t sA = sbase + cur * GSTG * 2;
        #pragma unroll
        for (int ks = 0; ks < 32; ks += 16) {
            uint32_t ah4[4][4], al4[4][4];
            #pragma unroll
            for (int mt = 0; mt < 4; mt++) {
                uint32_t ad = sA + ((wm + mt * 16 + a_row) * GAP + ks + a_col) * 2;
                ldsm4v(ah4[mt], ad);
                ldsm4v(al4[mt], ad + 128 * GAP * 2);
            }
            uint32_t bh4[2][4], bl4[2][4];
            #pragma unroll
            for (int nt2 = 0; nt2 < 2; nt2++) {
                uint32_t bd = sA + (2 * 128 * GAP + (wn + nt2 * 16 + b_row) * GAP + ks + b_col) * 2;
                ldsm4v(bh4[nt2], bd);
                ldsm4v(bl4[nt2], bd + 128 * GAP * 2);
            }
            #pragma unroll
            for (int mt = 0; mt < 4; mt++)
                #pragma unroll
                for (int nf = 0; nf < 4; nf++) {
                    uint32_t* bhp = &bh4[nf >> 1][(nf & 1) * 2];
                    uint32_t* blp = &bl4[nf >> 1][(nf & 1) * 2];
                    mma16816(acc[mt][nf], ah4[mt], bhp);
                    mma16816(acc[mt][nf], ah4[mt], blp);
                    mma16816(acc[mt][nf], al4[mt], bhp);
                }
        }
        __syncthreads();
    }

    #pragma unroll
    for (int mt = 0; mt < 4; mt++) {
        int r0 = m0 + wm + mt * 16 + g;
        #pragma unroll
        for (int nf = 0; nf < 4; nf++) {
            int c0 = n0 + wn + nf * 8 + 2 * tig;
            float2 v0, v1;
            v0.x = acc[mt][nf][0]; v0.y = acc[mt][nf][1];
            v1.x = acc[mt][nf][2]; v1.y = acc[mt][nf][3];
            if (bias) {
                float2 bb = *(const float2*)(bias + c0);
                v0.x += bb.x; v0.y += bb.y;
                v1.x += bb.x; v1.y += bb.y;
            }
            if (Ch) {
                uint32_t hh_, ll_;
                split2(v0.x, v0.y, hh_, ll_);
                *(uint32_t*)&Ch[(size_t)r0 * N + c0] = hh_;
                *(uint32_t*)&Cl[(size_t)r0 * N + c0] = ll_;
                split2(v1.x, v1.y, hh_, ll_);
                *(uint32_t*)&Ch[(size_t)(r0 + 8) * N + c0] = hh_;
                *(uint32_t*)&Cl[(size_t)(r0 + 8) * N + c0] = ll_;
            } else {
                *(float2*)(C + (size_t)r0 * N + c0) = v0;
                *(float2*)(C + (size_t)(r0 + 8) * N + c0) = v1;
            }
        }
    }
}

// ---------------- fused assemble + LN1 ----------------
__global__ void ln_fused_kernel(const float* __restrict__ gw, const float* __restrict__ bw,
                                const float* __restrict__ b1, const float* __restrict__ cls1,
                                const float* __restrict__ b2, const float* __restrict__ cls2) {
    int wid = threadIdx.x >> 5, lane = threadIdx.x & 31;
    long long row = (long long)blockIdx.x * 8 + wid;
    if (row >= ROWS_T) return;
    int b = (int)(row / NTOK), n = (int)(row % NTOK);

    const float* src; const float* badd = nullptr;
    if (n == 0)           { src = cls2; }
    else if (n <= NP)     { src = g_emb2 + ((size_t)(b * NP + (n - 1))) * EMBD; badd = b2; }
    else if (n == NP + 1) { src = cls1; }
    else                  { src = g_emb1 + ((size_t)(b * NP + (n - NP - 2))) * EMBD; badd = b1; }

    float v[8];
    float s = 0.f;
    #pragma unroll
    for (int j = 0; j < 8; j++) {
        int c = lane + 32 * j;
        v[j] = src[c] + (badd ? badd[c] : 0.f);
        s += v[j];
    }
    #pragma unroll
    for (int o = 16; o > 0; o >>= 1) s += __shfl_xor_sync(0xffffffffu, s, o);
    float mean = s * (1.f / EMBD);
    float s2 = 0.f;
    #pragma unroll
    for (int j = 0; j < 8; j++) { float d = v[j] - mean; s2 += d * d; }
    #pragma unroll
    for (int o = 16; o > 0; o >>= 1) s2 += __shfl_xor_sync(0xffffffffu, s2, o);
    float inv = rsqrtf(s2 * (1.f / EMBD) + 1e-5f);
    #pragma unroll
    for (int j = 0; j < 8; j++) {
        int c = lane + 32 * j;
        g_z[row * EMBD + c] = v[j];
        float o = (v[j] - mean) * inv * gw[c] + bw[c];
        __nv_bfloat16 h_, l_;
        split1(o, h_, l_);
        g_hh[row * EMBD + c] = h_;
        g_hl[row * EMBD + c] = l_;
    }
}

// z += LN(op)
__global__ void ln_res_kernel(const float* __restrict__ gw, const float* __restrict__ bw) {
    int wid = threadIdx.x >> 5, lane = threadIdx.x & 31;
    long long row = (long long)blockIdx.x * 8 + wid;
    if (row >= ROWS_T) return;
    const float* p = g_op + row * EMBD;
    float v[8];
    float s = 0.f;
    #pragma unroll
    for (int j = 0; j < 8; j++) { v[j] = p[lane + 32 * j]; s += v[j]; }
    #pragma unroll
    for (int o = 16; o > 0; o >>= 1) s += __shfl_xor_sync(0xffffffffu, s, o);
    float mean = s * (1.f / EMBD);
    float s2 = 0.f;
    #pragma unroll
    for (int j = 0; j < 8; j++) { float d = v[j] - mean; s2 += d * d; }
    #pragma unroll
    for (int o = 16; o > 0; o >>= 1) s2 += __shfl_xor_sync(0xffffffffu, s2, o);
    float inv = rsqrtf(s2 * (1.f / EMBD) + 1e-5f);
    #pragma unroll
    for (int j = 0; j < 8; j++) {
        int c = lane + 32 * j;
        g_z[row * EMBD + c] += (v[j] - mean) * inv * gw[c] + bw[c];
    }
}

// ---------------- tensor-core flash attention v5 ----------------
// BM=64, 128 threads, single-stage K/V (104 KB smem -> 2 blocks/SM).
#define FP 136
#define FA5_SMEM ((2 * 64 * FP + 4 * 64 * FP) * 2)   // 104448 bytes

__global__ __launch_bounds__(128)
void flash5_kernel() {
    extern __shared__ __nv_bfloat16 fsm5[];
    uint32_t sbase = smem_u32(fsm5);

    int tid = threadIdx.x;
    int lane = tid & 31, w = tid >> 5;
    int g = lane >> 2, tig = lane & 3;
    int m0 = blockIdx.x * 64;
    int b = blockIdx.y >> 1, h = blockIdx.y & 1;

    size_t rowbase = (size_t)b * NTOK * 768;
    const __nv_bfloat16* qh_g = g_qkvh + rowbase + h * DH;
    const __nv_bfloat16* ql_g = g_qkvl + rowbase + h * DH;
    const __nv_bfloat16* kh_g = qh_g + 256;
    const __nv_bfloat16* kl_g = ql_g + 256;
    const __nv_bfloat16* vh_g = qh_g + 512;
    const __nv_bfloat16* vl_g = ql_g + 512;

    uint32_t Qh_s = sbase;
    uint32_t Ql_s = sbase + 64 * FP * 2;
    uint32_t KV_s = sbase + 2 * 64 * FP * 2;   // Kh | Kl | Vh | Vl, single stage

    // Q tile
    for (int i = tid; i < 1024; i += 128) {
        int r = i >> 4, c8 = (i & 15) * 8;
        int src = m0 + r; if (src > NTOK - 1) src = NTOK - 1;
        cp16(Qh_s + (r * FP + c8) * 2, qh_g + (size_t)src * 768 + c8);
        cp16(Ql_s + (r * FP + c8) * 2, ql_g + (size_t)src * 768 + c8);
    }
    cp_commit();

    float oacc[16][4];
    #pragma unroll
    for (int i = 0; i < 16; i++)
        #pragma unroll
        for (int e = 0; e < 4; e++) oacc[i][e] = 0.f;
    float rm0 = -1e30f, rm1 = -1e30f, rl0 = 0.f, rl1 = 0.f;

    int a_row = (lane & 7) + ((lane >> 3) & 1) * 8;
    int a_col = ((lane >> 4) & 1) * 8;
    int b_row = (lane & 7) + ((lane >> 4) & 1) * 8;
    int b_col = ((lane >> 3) & 1) * 8;

    for (int nt = 0; nt < 7; nt++) {
        int n0c = nt * 64;
        // load K/V chunk (single buffer; previous compute finished at loop-end sync)
        for (int i = tid; i < 1024; i += 128) {
            int r = i >> 4, c8 = (i & 15) * 8;
            int src = n0c + r; if (src > NTOK - 1) src = NTOK - 1;
            cp16(KV_s + (r * FP + c8) * 2,               kh_g + (size_t)src * 768 + c8);
            cp16(KV_s + (64 * FP + r * FP + c8) * 2,     kl_g + (size_t)src * 768 + c8);
            cp16(KV_s + (2 * 64 * FP + r * FP + c8) * 2, vh_g + (size_t)src * 768 + c8);
            cp16(KV_s + (3 * 64 * FP + r * FP + c8) * 2, vl_g + (size_t)src * 768 + c8);
        }
        cp_commit();
        cp_wait0();
        __syncthreads();

        // S = Q K^T (3-pass split)
        float sacc[8][4];
        #pragma unroll
        for (int nf = 0; nf < 8; nf++)
            #pragma unroll
            for (int e = 0; e < 4; e++) sacc[nf][e] = 0.f;

        #pragma unroll
        for (int ks = 0; ks < 8; ks++) {
            int k0 = ks * 16;
            uint32_t ah[4], al[4];
            uint32_t qad = Qh_s + ((w * 16 + a_row) * FP + k0 + a_col) * 2;
            ldsm4v(ah, qad);
            ldsm4v(al, qad + 64 * FP * 2);
            #pragma unroll
            for (int nt2 = 0; nt2 < 4; nt2++) {
                uint32_t kad = KV_s + ((nt2 * 16 + b_row) * FP + k0 + b_col) * 2;
                uint32_t bh_[4], bl_[4];
                ldsm4v(bh_, kad);
                ldsm4v(bl_, kad + 64 * FP * 2);
                mma16816(sacc[nt2 * 2],     ah, &bh_[0]);
                mma16816(sacc[nt2 * 2],     ah, &bl_[0]);
                mma16816(sacc[nt2 * 2],     al, &bh_[0]);
                mma16816(sacc[nt2 * 2 + 1], ah, &bh_[2]);
                mma16816(sacc[nt2 * 2 + 1], ah, &bl_[2]);
                mma16816(sacc[nt2 * 2 + 1], al, &bh_[2]);
            }
        }

        // mask + online softmax
        float mx0 = -1e30f, mx1 = -1e30f;
        #pragma unroll
        for (int nf = 0; nf < 8; nf++) {
            int c0 = n0c + nf * 8 + 2 * tig;
            if (c0 >= NTOK)     { sacc[nf][0] = -1e30f; sacc[nf][2] = -1e30f; }
            if (c0 + 1 >= NTOK) { sacc[nf][1] = -1e30f; sacc[nf][3] = -1e30f; }
            mx0 = fmaxf(mx0, fmaxf(sacc[nf][0], sacc[nf][1]));
            mx1 = fmaxf(mx1, fmaxf(sacc[nf][2], sacc[nf][3]));
        }
        mx0 = fmaxf(mx0, __shfl_xor_sync(0xffffffffu, mx0, 1));
        mx0 = fmaxf(mx0, __shfl_xor_sync(0xffffffffu, mx0, 2));
        mx1 = fmaxf(mx1, __shfl_xor_sync(0xffffffffu, mx1, 1));
        mx1 = fmaxf(mx1, __shfl_xor_sync(0xffffffffu, mx1, 2));
        float nm0 = fmaxf(rm0, mx0), nm1 = fmaxf(rm1, mx1);
        float sc0 = fast_exp(rm0 - nm0), sc1 = fast_exp(rm1 - nm1);
        rm0 = nm0; rm1 = nm1;
        float rs0 = 0.f, rs1 = 0.f;
        uint32_t ph[8][2], pl[8][2];
        #pragma unroll
        for (int nf = 0; nf < 8; nf++) {
            float p0 = fast_exp(sacc[nf][0] - nm0);
            float p1 = fast_exp(sacc[nf][1] - nm0);
            float p2 = fast_exp(sacc[nf][2] - nm1);
            float p3 = fast_exp(sacc[nf][3] - nm1);
            rs0 += p0 + p1; rs1 += p2 + p3;
            split2(p0, p1, ph[nf][0], pl[nf][0]);
            split2(p2, p3, ph[nf][1], pl[nf][1]);
        }
        rs0 += __shfl_xor_sync(0xffffffffu, rs0, 1);
        rs0 += __shfl_xor_sync(0xffffffffu, rs0, 2);
        rs1 += __shfl_xor_sync(0xffffffffu, rs1, 1);
        rs1 += __shfl_xor_sync(0xffffffffu, rs1, 2);
        rl0 = rl0 * sc0 + rs0;
        rl1 = rl1 * sc1 + rs1;
        #pragma unroll
        for (int onf = 0; onf < 16; onf++) {
            oacc[onf][0] *= sc0; oacc[onf][1] *= sc0;
            oacc[onf][2] *= sc1; oacc[onf][3] *= sc1;
        }

        // O += P V
        uint32_t vbase = KV_s + 2 * 64 * FP * 2;
        #pragma unroll
        for (int ks = 0; ks < 4; ks++) {
            uint32_t ah[4] = {ph[2 * ks][0], ph[2 * ks][1], ph[2 * ks + 1][0], ph[2 * ks + 1][1]};
            uint32_t al[4] = {pl[2 * ks][0], pl[2 * ks][1], pl[2 * ks + 1][0], pl[2 * ks + 1][1]};
            #pragma unroll
            for (int dt = 0; dt < 8; dt++) {
                uint32_t vad = vbase + ((ks * 16 + a_row) * FP + dt * 16 + a_col) * 2;
                uint32_t bh_[4], bl_[4];
                ldsm4t(bh_, vad);
                ldsm4t(bl_, vad + 64 * FP * 2);
                mma16816(oacc[dt * 2],     ah, &bh_[0]);
                mma16816(oacc[dt * 2],     ah, &bl_[0]);
                mma16816(oacc[dt * 2],     al, &bh_[0]);
                mma16816(oacc[dt * 2 + 1], ah, &bh_[2]);
                mma16816(oacc[dt * 2 + 1], ah, &bl_[2]);
                mma16816(oacc[dt * 2 + 1], al, &bh_[2]);
            }
        }
        __syncthreads();
    }

    // epilogue
    float inv0 = 1.f / (rl0 * 16.f);
    float inv1 = 1.f / (rl1 * 16.f);
    int row0 = m0 + w * 16 + g, row1 = row0 + 8;
    #pragma unroll
    for (int onf = 0; onf < 16; onf++) {
        int col = h * DH + onf * 8 + 2 * tig;
        uint32_t hi, lo;
        if (row0 < NTOK) {
            split2(oacc[onf][0] * inv0, oacc[onf][1] * inv0, hi, lo);
            size_t off = ((size_t)b * NTOK + row0) * EMBD + col;
            *(uint32_t*)&g_oh[off] = hi;
            *(uint32_t*)&g_ol[off] = lo;
        }
        if (row1 < NTOK) {
            split2(oacc[onf][2] * inv1, oacc[onf][3] * inv1, hi, lo);
            size_t off = ((size_t)b * NTOK + row1) * EMBD + col;
            *(uint32_t*)&g_oh[off] = hi;
            *(uint32_t*)&g_ol[off] = lo;
        }
    }
}

// ---------------- head ----------------
__global__ void head_kernel(const float* __restrict__ lg, const float* __restrict__ lb,
                            const float* __restrict__ Wc, const float* __restrict__ bc,
                            float* __restrict__ out) {
    __shared__ float sh[8];
    int b = blockIdx.x;
    int c = threadIdx.x;
    const float* zb = g_z + (size_t)b * NTOK * EMBD;
    float s = 0.f;
    #pragma unroll 8
    for (int n = 0; n < NTOK; n++) s += zb[(size_t)n * EMBD + c];
    float pooled = s * (1.f / NTOK);
    float mean = block_sum_256(pooled, sh) * (1.f / EMBD);
    float d = pooled - mean;
    float var = block_sum_256(d * d, sh) * (1.f / EMBD);
    float ln = d * rsqrtf(var + 1e-5f) * lg[c] + lb[c];
    float l0 = block_sum_256(ln * Wc[c * 2 + 0], sh);
    float l1 = block_sum_256(ln * Wc[c * 2 + 1], sh);
    if (c == 0) {
        l0 += bc[0];
        l1 += bc[1];
        float mx = fmaxf(l0, l1);
        float lse = mx + logf(expf(l0 - mx) + expf(l1 - mx));
        out[b * 2 + 0] = l0 - lse;
        out[b * 2 + 1] = l1 - lse;
    }
}

// ---------------- launch ----------------
extern "C" void kernel_launch(void* const* d_in, const int* in_sizes, int n_in,
                              void* d_out, int out_size) {
    const float* x    = (const float*)d_in[0];
    const float* W1   = (const float*)d_in[1];
    const float* b1   = (const float*)d_in[2];
    const float* cls1 = (const float*)d_in[3];
    const float* W2   = (const float*)d_in[4];
    const float* b2   = (const float*)d_in[5];
    const float* cls2 = (const float*)d_in[6];
    const float* ln1g = (const float*)d_in[7];
    const float* ln1b = (const float*)d_in[8];
    const float* Wq   = (const float*)d_in[9];
    const float* bq   = (const float*)d_in[10];
    const float* Wk   = (const float*)d_in[11];
    const float* bk   = (const float*)d_in[12];
    const float* Wv   = (const float*)d_in[13];
    const float* bv   = (const float*)d_in[14];
    const float* Wp   = (const float*)d_in[15];
    const float* bp   = (const float*)d_in[16];
    const float* ln2g = (const float*)d_in[17];
    const float* ln2b = (const float*)d_in[18];
    const float* lncg = (const float*)d_in[19];
    const float* lncb = (const float*)d_in[20];
    const float* Wc   = (const float*)d_in[21];
    const float* bc   = (const float*)d_in[22];
    float* out = (float*)d_out;

    __nv_bfloat16 *p1h, *p1l, *p2h, *p2l, *hh, *hl, *oh, *ol, *qh, *ql;
    __nv_bfloat16 *w1h, *w1l, *w2h, *w2l, *wqh, *wql, *wph, *wpl;
    float *e1, *e2, *op_, *bqkv;
    cudaGetSymbolAddress((void**)&p1h, g_p1h);
    cudaGetSymbolAddress((void**)&p1l, g_p1l);
    cudaGetSymbolAddress((void**)&p2h, g_p2h);
    cudaGetSymbolAddress((void**)&p2l, g_p2l);
    cudaGetSymbolAddress((void**)&hh, g_hh);
    cudaGetSymbolAddress((void**)&hl, g_hl);
    cudaGetSymbolAddress((void**)&oh, g_oh);
    cudaGetSymbolAddress((void**)&ol, g_ol);
    cudaGetSymbolAddress((void**)&qh, g_qkvh);
    cudaGetSymbolAddress((void**)&ql, g_qkvl);
    cudaGetSymbolAddress((void**)&w1h, g_w1h);
    cudaGetSymbolAddress((void**)&w1l, g_w1l);
    cudaGetSymbolAddress((void**)&w2h, g_w2h);
    cudaGetSymbolAddress((void**)&w2l, g_w2l);
    cudaGetSymbolAddress((void**)&wqh, g_wqh);
    cudaGetSymbolAddress((void**)&wql, g_wql);
    cudaGetSymbolAddress((void**)&wph, g_wph);
    cudaGetSymbolAddress((void**)&wpl, g_wpl);
    cudaGetSymbolAddress((void**)&e1, g_emb1);
    cudaGetSymbolAddress((void**)&e2, g_emb2);
    cudaGetSymbolAddress((void**)&op_, g_op);
    cudaGetSymbolAddress((void**)&bqkv, g_bqkv);

    cudaFuncSetAttribute(gemm_mma2, cudaFuncAttributeMaxDynamicSharedMemorySize, GEMM2_SMEM);
    cudaFuncSetAttribute(flash5_kernel, cudaFuncAttributeMaxDynamicSharedMemorySize, FA5_SMEM);

    // launch 0: merged weight prep
    prep_kernel<<<(507904 + 255) / 256, 256>>>(W1, W2, Wp, Wq, Wk, Wv, bq, bk, bv);
    // launch 1: merged im2row
    im2row_kernel<<<(int)((N_IM1 + (size_t)ROWS_E * K2) / 256), 256>>>(x);

    // launches 2,3: patch embeds -> fp32
    gemm_mma2<<<dim3(2, ROWS_E / 128), 256, GEMM2_SMEM>>>(p1h, p1l, w1h, w1l, nullptr, e1, nullptr, nullptr, ROWS_E, EMBD, K1);
    gemm_mma2<<<dim3(2, ROWS_E / 128), 256, GEMM2_SMEM>>>(p2h, p2l, w2h, w2l, nullptr, e2, nullptr, nullptr, ROWS_E, EMBD, K2);

    // launch 4: fused assemble + LN1
    ln_fused_kernel<<<ROWS_T / 8, 256>>>(ln1g, ln1b, b1, cls1, b2, cls2);

    // launch 5: fused QKV -> split bf16   (ncu -s 5 lands here)
    gemm_mma2<<<dim3(6, ROWS_T / 128), 256, GEMM2_SMEM>>>(hh, hl, wqh, wql, bqkv, nullptr, qh, ql, ROWS_T, 768, EMBD);

    // launch 6: flash attention (BM=64, 2 blocks/SM)
    flash5_kernel<<<dim3(7, BATCH * HEADS), 128, FA5_SMEM>>>();

    // launch 7: output projection -> fp32
    gemm_mma2<<<dim3(2, ROWS_T / 128), 256, GEMM2_SMEM>>>(oh, ol, wph, wpl, bp, op_, nullptr, nullptr, ROWS_T, EMBD, EMBD);

    // launches 8,9
    ln_res_kernel<<<ROWS_T / 8, 256>>>(ln2g, ln2b);
    head_kernel<<<BATCH, 256>>>(lncg, lncb, Wc, bc, out);
}